// round 1
// baseline (speedup 1.0000x reference)
#include <cuda_runtime.h>
#include <cuda_bf16.h>

#define BATCH 32
#define LEN   512
#define DIM   384           // floats per row = 96 float4
#define WARPS_PER_BLOCK 16

// Scratch (no cudaMalloc allowed): cumsum table + row totals.
__device__ int g_cs[BATCH * LEN];
__device__ int g_total[BATCH];

// Kernel 1: per-row inclusive scan (Hillis-Steele in shared memory).
__global__ void __launch_bounds__(LEN) scan_kernel(const int* __restrict__ x) {
    __shared__ int s[LEN];
    const int b = blockIdx.x;
    const int tid = threadIdx.x;
    s[tid] = x[b * LEN + tid];
    __syncthreads();
#pragma unroll
    for (int off = 1; off < LEN; off <<= 1) {
        int add = (tid >= off) ? s[tid - off] : 0;
        __syncthreads();
        s[tid] += add;
        __syncthreads();
    }
    g_cs[b * LEN + tid] = s[tid];
    if (tid == LEN - 1) g_total[b] = s[tid];
}

// Kernel 2: one warp per timestep t. Binary-search token containing t,
// then stream the pos_enc row (or zeros) to the output as float4s.
__global__ void __launch_bounds__(WARPS_PER_BLOCK * 32)
emit_kernel(const float* __restrict__ pe, float* __restrict__ out, int T) {
    __shared__ int s_cs[LEN];
    const int b   = blockIdx.y;
    const int tid = threadIdx.x;

    // 512 threads load the 512-entry cumsum row for this batch.
    s_cs[tid] = g_cs[b * LEN + tid];
    const int total = g_total[b];
    __syncthreads();

    const int warp = tid >> 5;
    const int lane = tid & 31;
    const int t = blockIdx.x * WARPS_PER_BLOCK + warp;
    if (t >= T) return;

    float4* dst = reinterpret_cast<float4*>(out + ((size_t)b * T + t) * DIM);

    if (t < total) {
        // searchsorted(cs, t, side='right'): first index with cs[idx] > t.
        int lo = 0, hi = LEN;
        while (lo < hi) {
            int mid = (lo + hi) >> 1;
            if (s_cs[mid] > t) hi = mid; else lo = mid + 1;
        }
        const int tok   = lo;                    // guaranteed <= LEN-1 since t < total
        const int start = (tok > 0) ? s_cs[tok - 1] : 0;
        const int pos   = t - start;             // < 16 since x values < 16

        const float4* src = reinterpret_cast<const float4*>(pe + (size_t)pos * DIM);
        // 96 float4 per row, 32 lanes -> 3 per lane, fully coalesced.
        float4 v0 = src[lane];
        float4 v1 = src[lane + 32];
        float4 v2 = src[lane + 64];
        dst[lane]      = v0;
        dst[lane + 32] = v1;
        dst[lane + 64] = v2;
    } else {
        const float4 z = make_float4(0.f, 0.f, 0.f, 0.f);
        dst[lane]      = z;
        dst[lane + 32] = z;
        dst[lane + 64] = z;
    }
}

extern "C" void kernel_launch(void* const* d_in, const int* in_sizes, int n_in,
                              void* d_out, int out_size) {
    // Inputs per metadata order: x (32*512 int32), pos_enc (5000*384 float32).
    // Disambiguate defensively by element count.
    const int*   x;
    const float* pe;
    if (in_sizes[0] == BATCH * LEN) {
        x  = (const int*)d_in[0];
        pe = (const float*)d_in[1];
    } else {
        x  = (const int*)d_in[1];
        pe = (const float*)d_in[0];
    }

    const int T = out_size / (BATCH * DIM);
    float* out = (float*)d_out;

    scan_kernel<<<BATCH, LEN>>>(x);

    dim3 grid((T + WARPS_PER_BLOCK - 1) / WARPS_PER_BLOCK, BATCH);
    emit_kernel<<<grid, WARPS_PER_BLOCK * 32>>>(pe, out, T);
}